// round 7
// baseline (speedup 1.0000x reference)
#include <cuda_runtime.h>

#define NN 100000
#define NE 3200000
#define NEG 0.2f

// ---- scratch (device globals; no allocations allowed) ----
__device__ __align__(16) float4 g_h1[NN * 2];   // h1 [NN,8]
__device__ float g_as1[NN];
__device__ float g_ad1[NN];
__device__ __align__(16) float4 g_n2[NN];       // (h2x, h2y, as2, ad2)
__device__ int   g_deg[NN];
__device__ int   g_base[NN];
__device__ int   g_wp[NN];
__device__ int   g_csr[NE];                     // src ids grouped by dst
__device__ int   g_cursor;

// ---- layer-1 node kernel: h1 = x@W1, logits; zero deg/cursor ----
__global__ __launch_bounds__(128) void k_node1(
    const float* __restrict__ x, const float* __restrict__ W1,
    const float* __restrict__ as1, const float* __restrict__ ad1)
{
    __shared__ float xs[128 * 37];
    __shared__ float Ws[36 * 8];
    __shared__ float av[8], dv[8];
    const int t = threadIdx.x;
    const int base = blockIdx.x * 128;

    if (base == 0 && t == 0) g_cursor = 0;
    for (int i = t; i < 36 * 8; i += 128) Ws[i] = W1[i];
    if (t < 8) { av[t] = as1[t]; dv[t] = ad1[t]; }

    int nrows = NN - base; if (nrows > 128) nrows = 128;
    for (int i = t; i < nrows * 36; i += 128)
        xs[(i / 36) * 37 + (i % 36)] = x[base * 36 + i];
    __syncthreads();

    const int node = base + t;
    if (node >= NN) return;

    float h[8];
#pragma unroll
    for (int k = 0; k < 8; k++) h[k] = 0.f;
#pragma unroll
    for (int j = 0; j < 36; j++) {
        const float xv = xs[t * 37 + j];
#pragma unroll
        for (int k = 0; k < 8; k++) h[k] = fmaf(xv, Ws[j * 8 + k], h[k]);
    }
    g_h1[node * 2]     = make_float4(h[0], h[1], h[2], h[3]);
    g_h1[node * 2 + 1] = make_float4(h[4], h[5], h[6], h[7]);

    float s = 0.f, d = 0.f;
#pragma unroll
    for (int k = 0; k < 8; k++) { s = fmaf(h[k], av[k], s); d = fmaf(h[k], dv[k], d); }
    g_as1[node] = s;
    g_ad1[node] = d;
    g_deg[node] = 0;
}

// ---- histogram of dst degrees ----
__global__ __launch_bounds__(256) void k_hist(const int* __restrict__ ei)
{
    const int e = blockIdx.x * 256 + threadIdx.x;
    if (e >= NE) return;
    const int d = ei[NE + e];
    if ((unsigned)d < NN) atomicAdd(&g_deg[d], 1);
}

// ---- segment assignment: block-local exclusive scan + bump cursor ----
__global__ __launch_bounds__(256) void k_seg()
{
    __shared__ int sc[256];
    __shared__ int blockBase;
    const int t = threadIdx.x;
    const int n = blockIdx.x * 256 + t;
    int deg = (n < NN) ? g_deg[n] : 0;
    sc[t] = deg;
    __syncthreads();
    // Hillis-Steele inclusive scan
    int v = deg;
#pragma unroll
    for (int off = 1; off < 256; off <<= 1) {
        int add = (t >= off) ? sc[t - off] : 0;
        __syncthreads();
        v += add; sc[t] = v;
        __syncthreads();
    }
    if (t == 255) blockBase = atomicAdd(&g_cursor, v);
    __syncthreads();
    if (n < NN) {
        const int excl = v - deg;          // exclusive scan value
        const int b = blockBase + excl;
        g_base[n] = b;
        g_wp[n]   = b;
    }
}

// ---- scatter src ids into CSR slots ----
__global__ __launch_bounds__(256) void k_scatter(const int* __restrict__ ei)
{
    const int e = blockIdx.x * 256 + threadIdx.x;
    if (e >= NE) return;
    const int s = ei[e];
    const int d = ei[NE + e];
    if ((unsigned)s >= NN || (unsigned)d >= NN) return;
    const int slot = atomicAdd(&g_wp[d], 1);
    g_csr[slot] = s;
}

// ---- layer-1 pull: one warp per dst; fused node2 epilogue ----
__global__ __launch_bounds__(256) void k_pull1(
    const float* __restrict__ b1, const float* __restrict__ W2,
    const float* __restrict__ as2, const float* __restrict__ ad2)
{
    const int wid = (blockIdx.x * 256 + threadIdx.x) >> 5;
    if (wid >= NN) return;
    const int lane = threadIdx.x & 31;

    const int start = g_base[wid];
    const int deg   = g_deg[wid];
    const float ad  = g_ad1[wid];

    float a0 = 0.f, a1 = 0.f, a2 = 0.f, a3 = 0.f;
    float a4 = 0.f, a5 = 0.f, a6 = 0.f, a7 = 0.f, den = 0.f;

    for (int i = lane; i < deg; i += 32) {
        const int s = g_csr[start + i];
        float ev = g_as1[s] + ad;
        ev = ev > 0.f ? ev : NEG * ev;
        const float w = __expf(ev);
        const float4 h0 = g_h1[s * 2];
        const float4 h1 = g_h1[s * 2 + 1];
        a0 = fmaf(w, h0.x, a0); a1 = fmaf(w, h0.y, a1);
        a2 = fmaf(w, h0.z, a2); a3 = fmaf(w, h0.w, a3);
        a4 = fmaf(w, h1.x, a4); a5 = fmaf(w, h1.y, a5);
        a6 = fmaf(w, h1.z, a6); a7 = fmaf(w, h1.w, a7);
        den += w;
    }
#pragma unroll
    for (int off = 16; off > 0; off >>= 1) {
        a0 += __shfl_down_sync(0xffffffffu, a0, off);
        a1 += __shfl_down_sync(0xffffffffu, a1, off);
        a2 += __shfl_down_sync(0xffffffffu, a2, off);
        a3 += __shfl_down_sync(0xffffffffu, a3, off);
        a4 += __shfl_down_sync(0xffffffffu, a4, off);
        a5 += __shfl_down_sync(0xffffffffu, a5, off);
        a6 += __shfl_down_sync(0xffffffffu, a6, off);
        a7 += __shfl_down_sync(0xffffffffu, a7, off);
        den += __shfl_down_sync(0xffffffffu, den, off);
    }
    if (lane == 0) {
        const float inv = den > 0.f ? 1.0f / den : 0.f;
        float h[8];
        h[0] = fmaxf(fmaf(a0, inv, __ldg(&b1[0])), 0.f);
        h[1] = fmaxf(fmaf(a1, inv, __ldg(&b1[1])), 0.f);
        h[2] = fmaxf(fmaf(a2, inv, __ldg(&b1[2])), 0.f);
        h[3] = fmaxf(fmaf(a3, inv, __ldg(&b1[3])), 0.f);
        h[4] = fmaxf(fmaf(a4, inv, __ldg(&b1[4])), 0.f);
        h[5] = fmaxf(fmaf(a5, inv, __ldg(&b1[5])), 0.f);
        h[6] = fmaxf(fmaf(a6, inv, __ldg(&b1[6])), 0.f);
        h[7] = fmaxf(fmaf(a7, inv, __ldg(&b1[7])), 0.f);
        float o0 = 0.f, o1 = 0.f;
#pragma unroll
        for (int k = 0; k < 8; k++) {
            o0 = fmaf(h[k], __ldg(&W2[k * 2 + 0]), o0);
            o1 = fmaf(h[k], __ldg(&W2[k * 2 + 1]), o1);
        }
        const float s2 = fmaf(o0, __ldg(&as2[0]), o1 * __ldg(&as2[1]));
        const float d2 = fmaf(o0, __ldg(&ad2[0]), o1 * __ldg(&ad2[1]));
        g_n2[wid] = make_float4(o0, o1, s2, d2);
    }
}

// ---- layer-2 pull: one warp per dst; fused log_softmax epilogue ----
__global__ __launch_bounds__(256) void k_pull2(
    const float* __restrict__ b2, float* __restrict__ out)
{
    const int wid = (blockIdx.x * 256 + threadIdx.x) >> 5;
    if (wid >= NN) return;
    const int lane = threadIdx.x & 31;

    const int start = g_base[wid];
    const int deg   = g_deg[wid];
    const float ad  = g_n2[wid].w;

    float a0 = 0.f, a1 = 0.f, den = 0.f;
    for (int i = lane; i < deg; i += 32) {
        const int s = g_csr[start + i];
        const float4 ns = g_n2[s];           // h2x, h2y, as2, -
        float ev = ns.z + ad;
        ev = ev > 0.f ? ev : NEG * ev;
        const float w = __expf(ev);
        a0 = fmaf(w, ns.x, a0);
        a1 = fmaf(w, ns.y, a1);
        den += w;
    }
#pragma unroll
    for (int off = 16; off > 0; off >>= 1) {
        a0  += __shfl_down_sync(0xffffffffu, a0, off);
        a1  += __shfl_down_sync(0xffffffffu, a1, off);
        den += __shfl_down_sync(0xffffffffu, den, off);
    }
    if (lane == 0) {
        const float inv = den > 0.f ? 1.0f / den : 0.f;
        const float o0 = fmaf(a0, inv, __ldg(&b2[0]));
        const float o1 = fmaf(a1, inv, __ldg(&b2[1]));
        const float m = fmaxf(o0, o1);
        const float lse = m + logf(expf(o0 - m) + expf(o1 - m));
        ((float2*)out)[wid] = make_float2(o0 - lse, o1 - lse);
    }
}

extern "C" void kernel_launch(void* const* d_in, const int* in_sizes, int n_in,
                              void* d_out, int out_size)
{
    // ---- identify inputs by element count (robust to metadata ordering) ----
    int ix = -1, ie = -1, iw1 = -1, iw2 = -1;
    int i8[3] = {-1, -1, -1}, n8 = 0;
    int i2[3] = {-1, -1, -1}, n2 = 0;
    for (int i = 0; i < n_in; i++) {
        switch (in_sizes[i]) {
            case 3600000: ix = i; break;
            case 6400000: ie = i; break;
            case 288:     iw1 = i; break;
            case 16:      iw2 = i; break;
            case 8:  if (n8 < 3) i8[n8++] = i; break;
            case 2:  if (n2 < 3) i2[n2++] = i; break;
            default: break;
        }
    }
    int ias1, iad1, ib1, ias2, iad2, ib2;
    if (ix == 0) { ias1 = i8[0]; iad1 = i8[1]; ib1 = i8[2];
                   ias2 = i2[0]; iad2 = i2[1]; ib2 = i2[2]; }
    else         { iad1 = i8[0]; ias1 = i8[1]; ib1 = i8[2];
                   iad2 = i2[0]; ias2 = i2[1]; ib2 = i2[2]; }

    const float* x   = (const float*)d_in[ix];
    const int*   ei  = (const int*)d_in[ie];
    const float* W1  = (const float*)d_in[iw1];
    const float* as1 = (const float*)d_in[ias1];
    const float* ad1 = (const float*)d_in[iad1];
    const float* b1  = (const float*)d_in[ib1];
    const float* W2  = (const float*)d_in[iw2];
    const float* as2 = (const float*)d_in[ias2];
    const float* ad2 = (const float*)d_in[iad2];
    const float* b2  = (const float*)d_in[ib2];
    float* out = (float*)d_out;

    const int nb_node1 = (NN + 127) / 128;
    const int nb_edge  = (NE + 255) / 256;
    const int nb_seg   = (NN + 255) / 256;
    const int nb_pull  = (NN * 32 + 255) / 256;   // one warp per node

    k_node1  <<<nb_node1, 128>>>(x, W1, as1, ad1);
    k_hist   <<<nb_edge, 256>>>(ei);
    k_seg    <<<nb_seg, 256>>>();
    k_scatter<<<nb_edge, 256>>>(ei);
    k_pull1  <<<nb_pull, 256>>>(b1, W2, as2, ad2);
    k_pull2  <<<nb_pull, 256>>>(b2, out);
}

// round 8
// speedup vs baseline: 1.2721x; 1.2721x over previous
#include <cuda_runtime.h>

#define NN 100000
#define NE 3200000
#define NEG 0.2f

// ---- scratch (device globals; no allocations allowed) ----
__device__ __align__(16) float4 g_h1[NN * 2];     // h1 [NN,8]
__device__ float  g_as1[NN];
__device__ float  g_ad1[NN];
__device__ __align__(16) float4 g_acc1v[NN * 3];  // [0],[1]=vec acc, [2].x=den
__device__ __align__(16) float4 g_n2[NN];         // (h2x, h2y, as2, ad2)
__device__ __align__(16) float4 g_acc2v[NN];      // (accx, accy, den, pad)

// ---- layer-1 node kernel: h1 = x@W1, attention logits, zero accumulators ----
__global__ __launch_bounds__(128) void k_node1(
    const float* __restrict__ x, const float* __restrict__ W1,
    const float* __restrict__ as1, const float* __restrict__ ad1)
{
    __shared__ float xs[128 * 37];   // pad 36->37: conflict-free
    __shared__ float Ws[36 * 8];
    __shared__ float av[8], dv[8];
    const int t = threadIdx.x;
    const int base = blockIdx.x * 128;

    for (int i = t; i < 36 * 8; i += 128) Ws[i] = W1[i];
    if (t < 8) { av[t] = as1[t]; dv[t] = ad1[t]; }

    int nrows = NN - base; if (nrows > 128) nrows = 128;
    for (int i = t; i < nrows * 36; i += 128)
        xs[(i / 36) * 37 + (i % 36)] = x[base * 36 + i];
    __syncthreads();

    const int node = base + t;
    if (node >= NN) return;

    float h[8];
#pragma unroll
    for (int k = 0; k < 8; k++) h[k] = 0.f;
#pragma unroll
    for (int j = 0; j < 36; j++) {
        const float xv = xs[t * 37 + j];
#pragma unroll
        for (int k = 0; k < 8; k++) h[k] = fmaf(xv, Ws[j * 8 + k], h[k]);
    }
    g_h1[node * 2]     = make_float4(h[0], h[1], h[2], h[3]);
    g_h1[node * 2 + 1] = make_float4(h[4], h[5], h[6], h[7]);

    float s = 0.f, d = 0.f;
#pragma unroll
    for (int k = 0; k < 8; k++) { s = fmaf(h[k], av[k], s); d = fmaf(h[k], dv[k], d); }
    g_as1[node] = s;
    g_ad1[node] = d;

    const float4 z4 = make_float4(0.f, 0.f, 0.f, 0.f);
    g_acc1v[node * 3]     = z4;
    g_acc1v[node * 3 + 1] = z4;
    g_acc1v[node * 3 + 2] = z4;
    g_acc2v[node]         = z4;
}

// ---- layer-1 edge kernel: 2 edges/thread, int2 index loads ----
__global__ __launch_bounds__(256) void k_edge1(
    const int2* __restrict__ eis, const int2* __restrict__ eid)
{
    const int t = blockIdx.x * 256 + threadIdx.x;
    if (t >= NE / 2) return;
    const int2 sp = eis[t];
    const int2 dp = eid[t];

    const bool okA = (unsigned)sp.x < NN && (unsigned)dp.x < NN;
    const bool okB = (unsigned)sp.y < NN && (unsigned)dp.y < NN;

    // issue all gathers up front (MLP)
    float asA = 0.f, adA = 0.f, asB = 0.f, adB = 0.f;
    float4 h0A, h1A, h0B, h1B;
    if (okA) {
        asA = g_as1[sp.x]; adA = g_ad1[dp.x];
        h0A = g_h1[sp.x * 2]; h1A = g_h1[sp.x * 2 + 1];
    }
    if (okB) {
        asB = g_as1[sp.y]; adB = g_ad1[dp.y];
        h0B = g_h1[sp.y * 2]; h1B = g_h1[sp.y * 2 + 1];
    }

    if (okA) {
        float ev = asA + adA;
        ev = ev > 0.f ? ev : NEG * ev;
        const float w = __expf(ev);
        atomicAdd(&g_acc1v[dp.x * 3],
                  make_float4(w * h0A.x, w * h0A.y, w * h0A.z, w * h0A.w));
        atomicAdd(&g_acc1v[dp.x * 3 + 1],
                  make_float4(w * h1A.x, w * h1A.y, w * h1A.z, w * h1A.w));
        atomicAdd((float*)&g_acc1v[dp.x * 3 + 2], w);
    }
    if (okB) {
        float ev = asB + adB;
        ev = ev > 0.f ? ev : NEG * ev;
        const float w = __expf(ev);
        atomicAdd(&g_acc1v[dp.y * 3],
                  make_float4(w * h0B.x, w * h0B.y, w * h0B.z, w * h0B.w));
        atomicAdd(&g_acc1v[dp.y * 3 + 1],
                  make_float4(w * h1B.x, w * h1B.y, w * h1B.z, w * h1B.w));
        atomicAdd((float*)&g_acc1v[dp.y * 3 + 2], w);
    }
}

// ---- layer-2 node kernel: relu(agg1+b1) @ W2; pack (h2, as2, ad2) ----
__global__ __launch_bounds__(256) void k_node2(
    const float* __restrict__ b1, const float* __restrict__ W2,
    const float* __restrict__ as2, const float* __restrict__ ad2)
{
    const int i = blockIdx.x * 256 + threadIdx.x;
    if (i >= NN) return;

    const float4 a0 = g_acc1v[i * 3];
    const float4 a1 = g_acc1v[i * 3 + 1];
    const float den = g_acc1v[i * 3 + 2].x;
    const float inv = den > 0.f ? 1.0f / den : 0.f;

    float h[8];
    h[0] = fmaxf(fmaf(a0.x, inv, __ldg(&b1[0])), 0.f);
    h[1] = fmaxf(fmaf(a0.y, inv, __ldg(&b1[1])), 0.f);
    h[2] = fmaxf(fmaf(a0.z, inv, __ldg(&b1[2])), 0.f);
    h[3] = fmaxf(fmaf(a0.w, inv, __ldg(&b1[3])), 0.f);
    h[4] = fmaxf(fmaf(a1.x, inv, __ldg(&b1[4])), 0.f);
    h[5] = fmaxf(fmaf(a1.y, inv, __ldg(&b1[5])), 0.f);
    h[6] = fmaxf(fmaf(a1.z, inv, __ldg(&b1[6])), 0.f);
    h[7] = fmaxf(fmaf(a1.w, inv, __ldg(&b1[7])), 0.f);

    float o0 = 0.f, o1 = 0.f;
#pragma unroll
    for (int k = 0; k < 8; k++) {
        o0 = fmaf(h[k], __ldg(&W2[k * 2 + 0]), o0);
        o1 = fmaf(h[k], __ldg(&W2[k * 2 + 1]), o1);
    }
    const float s2 = fmaf(o0, __ldg(&as2[0]), o1 * __ldg(&as2[1]));
    const float d2 = fmaf(o0, __ldg(&ad2[0]), o1 * __ldg(&ad2[1]));
    g_n2[i] = make_float4(o0, o1, s2, d2);
}

// ---- layer-2 edge kernel: 2 edges/thread, single float4 RED each ----
__global__ __launch_bounds__(256) void k_edge2(
    const int2* __restrict__ eis, const int2* __restrict__ eid)
{
    const int t = blockIdx.x * 256 + threadIdx.x;
    if (t >= NE / 2) return;
    const int2 sp = eis[t];
    const int2 dp = eid[t];

    const bool okA = (unsigned)sp.x < NN && (unsigned)dp.x < NN;
    const bool okB = (unsigned)sp.y < NN && (unsigned)dp.y < NN;

    float4 nsA, nsB;
    float adA = 0.f, adB = 0.f;
    if (okA) { nsA = g_n2[sp.x]; adA = g_n2[dp.x].w; }
    if (okB) { nsB = g_n2[sp.y]; adB = g_n2[dp.y].w; }

    if (okA) {
        float ev = nsA.z + adA;
        ev = ev > 0.f ? ev : NEG * ev;
        const float w = __expf(ev);
        atomicAdd(&g_acc2v[dp.x], make_float4(w * nsA.x, w * nsA.y, w, 0.f));
    }
    if (okB) {
        float ev = nsB.z + adB;
        ev = ev > 0.f ? ev : NEG * ev;
        const float w = __expf(ev);
        atomicAdd(&g_acc2v[dp.y], make_float4(w * nsB.x, w * nsB.y, w, 0.f));
    }
}

// ---- final node kernel: normalize, +b2, log_softmax(2) ----
__global__ __launch_bounds__(256) void k_node3(
    const float* __restrict__ b2, float* __restrict__ out)
{
    const int i = blockIdx.x * 256 + threadIdx.x;
    if (i >= NN) return;

    const float4 a = g_acc2v[i];
    const float inv = a.z > 0.f ? 1.0f / a.z : 0.f;
    const float o0 = fmaf(a.x, inv, __ldg(&b2[0]));
    const float o1 = fmaf(a.y, inv, __ldg(&b2[1]));
    const float m = fmaxf(o0, o1);
    const float lse = m + logf(expf(o0 - m) + expf(o1 - m));
    ((float2*)out)[i] = make_float2(o0 - lse, o1 - lse);
}

extern "C" void kernel_launch(void* const* d_in, const int* in_sizes, int n_in,
                              void* d_out, int out_size)
{
    // ---- identify inputs by element count (robust to metadata ordering) ----
    int ix = -1, ie = -1, iw1 = -1, iw2 = -1;
    int i8[3] = {-1, -1, -1}, n8 = 0;
    int i2[3] = {-1, -1, -1}, n2 = 0;
    for (int i = 0; i < n_in; i++) {
        switch (in_sizes[i]) {
            case 3600000: ix = i; break;          // x [100000, 36] f32
            case 6400000: ie = i; break;          // edge_index [2, 3200000] i32
            case 288:     iw1 = i; break;         // W1 [36, 8]
            case 16:      iw2 = i; break;         // W2 [8, 2]
            case 8:  if (n8 < 3) i8[n8++] = i; break;  // a_src1/a_dst1/b1
            case 2:  if (n2 < 3) i2[n2++] = i; break;  // a_src2/a_dst2/b2
            default: break;
        }
    }
    int ias1, iad1, ib1, ias2, iad2, ib2;
    if (ix == 0) { ias1 = i8[0]; iad1 = i8[1]; ib1 = i8[2];
                   ias2 = i2[0]; iad2 = i2[1]; ib2 = i2[2]; }
    else         { iad1 = i8[0]; ias1 = i8[1]; ib1 = i8[2];
                   iad2 = i2[0]; ias2 = i2[1]; ib2 = i2[2]; }

    const float* x   = (const float*)d_in[ix];
    const int*   ei  = (const int*)d_in[ie];     // int32 (JAX x64 disabled)
    const float* W1  = (const float*)d_in[iw1];
    const float* as1 = (const float*)d_in[ias1];
    const float* ad1 = (const float*)d_in[iad1];
    const float* b1  = (const float*)d_in[ib1];
    const float* W2  = (const float*)d_in[iw2];
    const float* as2 = (const float*)d_in[ias2];
    const float* ad2 = (const float*)d_in[iad2];
    const float* b2  = (const float*)d_in[ib2];
    float* out = (float*)d_out;

    const int2* eis = (const int2*)ei;           // src row, pairs
    const int2* eid = (const int2*)(ei + NE);    // dst row, pairs

    const int nb_node1 = (NN + 127) / 128;
    const int nb_node  = (NN + 255) / 256;
    const int nb_edge2 = (NE / 2 + 255) / 256;   // 2 edges per thread

    k_node1<<<nb_node1, 128>>>(x, W1, as1, ad1);
    k_edge1<<<nb_edge2, 256>>>(eis, eid);
    k_node2<<<nb_node, 256>>>(b1, W2, as2, ad2);
    k_edge2<<<nb_edge2, 256>>>(eis, eid);
    k_node3<<<nb_node, 256>>>(b2, out);
}